// round 14
// baseline (speedup 1.0000x reference)
#include <cuda_runtime.h>
#include <cuda_bf16.h>
#include <cstdint>

#define NSTEP   365
#define NGRID   50000
#define PRECS_F 1e-5f
#define BLK     352                     // 11 warps; 143 blocks -> 1 block/SM, balanced
#define CHUNK   16                      // timesteps staged per smem buffer
#define ROWB    (BLK * 12)              // 4224 B of x per timestep per block
#define BUFB    (ROWB * CHUNK)          // 67584 B per buffer
#define NBUF    3                       // triple buffer: 202752 B smem
#define NCH     ((NSTEP + CHUNK - 1) / CHUNK)   // 23 chunks (22 full + 13-step tail)
#define TAILNS  (NSTEP - (NCH - 1) * CHUNK)     // 13

extern __shared__ char smem_raw[];      // NBUF * BUFB

// Stage `nrows` timestep-rows of this block's x slice into sbuf via cp.async.
// Every thread executes the commit (uniform group counting).
__device__ __forceinline__ void stage_chunk(const char* __restrict__ xbase,
                                            char* sbuf, int t0, int nrows,
                                            int g0, int perrow, int tid)
{
    if (tid < perrow) {
        const char* gsrc = xbase + (size_t)t0 * (size_t)(NGRID * 12)
                                 + (size_t)g0 * 12 + (size_t)tid * 16;
        uint32_t sdst = (uint32_t)__cvta_generic_to_shared(sbuf) + tid * 16;
#pragma unroll
        for (int r = 0; r < CHUNK; r++) {
            if (r < nrows) {
                asm volatile("cp.async.cg.shared.global [%0], [%1], 16;\n"
                             :: "r"(sdst + r * ROWB),
                                "l"(gsrc + (size_t)r * (size_t)(NGRID * 12))
                             : "memory");
            }
        }
    }
    asm volatile("cp.async.commit_group;\n" ::: "memory");
}

// One HBV timestep at compile-time step index s.
// SW carries soil_wetness computed at the END of the previous step (from that
// step's final SM) — mathematically identical to computing it here, but the
// MUFU chain (LG2+EX2, ~36 cyc) overlaps the response routine + next snow
// routine instead of sitting on the SM critical path.
#define HBV_STEP(s) do {                                                        \
    const float P = sb[(s) * (BLK * 3) + 0];                                    \
    const float T = sb[(s) * (BLK * 3) + 1];                                    \
    const float E = sb[(s) * (BLK * 3) + 2];                                    \
    const float RAIN = (T >= TT) ? P : 0.0f;                                    \
    SNOWPACK += P - RAIN;                                                       \
    const float melt = fminf(fmaxf(fmaf(CFMAX, T, -CFMAX_TT), 0.0f), SNOWPACK); \
    MELTWATER += melt;                                                          \
    SNOWPACK  -= melt;                                                          \
    const float refr = fminf(fmaxf(fmaf(-CFRC, T, CFRC_TT), 0.0f), MELTWATER);  \
    SNOWPACK  += refr;                                                          \
    MELTWATER -= refr;                                                          \
    const float tosoil = fmaxf(fmaf(-CWH, SNOWPACK, MELTWATER), 0.0f);          \
    MELTWATER -= tosoil;                                                        \
    const float rt       = RAIN + tosoil;                                       \
    const float recharge = rt * SW;               /* SW from previous step */   \
    SM += rt - recharge;                                                        \
    const float excess = fmaxf(SM - FC, 0.0f);                                  \
    SM = fminf(SM, FC);                           /* == SM - excess */          \
    const float evapf = __saturatef(SM * invLPFC);                              \
    const float ETact = fminf(SM, E * evapf);                                   \
    SM = fmaxf(SM - ETact, PRECS_F);                                            \
    SW = __saturatef(__powf(SM * invFC, BETA));   /* for NEXT step; off-chain */\
    SUZ += recharge + excess;                                                   \
    const float PERC = fminf(SUZ, PERCp);                                       \
    SUZ -= PERC;                                  /* S2 */                      \
    const float suz3 = fmaf(-K0, fmaxf(SUZ - UZL, 0.0f), SUZ) * K1C; /* S4 */   \
    SLZ += PERC;                                  /* L1 */                      \
    const float slz2 = SLZ * K2C;                 /* L2 */                      \
    __stcs(o + (size_t)(s) * NGRID, (SUZ - suz3) + (SLZ - slz2));               \
    SUZ = suz3;                                                                 \
    SLZ = slz2;                                                                 \
} while (0)

__global__ __launch_bounds__(BLK, 1)
void hbv_kernel(const float* __restrict__ x,
                const float* __restrict__ params,
                float* __restrict__ out)
{
    const int tid = threadIdx.x;
    const int g0  = blockIdx.x * BLK;
    const int g   = g0 + tid;
    const bool active = (g < NGRID);

    const int ncells = min(BLK, NGRID - g0);       // 352, or 16 for last block
    const int perrow = (ncells * 12) / 16;         // 16B cp.async ops per row

    // ---- kick off the first two chunk loads immediately (depth-2 prefetch) ----
    const char* xb = (const char*)x;
    stage_chunk(xb, smem_raw,        0,     CHUNK, g0, perrow, tid);
    stage_chunk(xb, smem_raw + BUFB, CHUNK, CHUNK, g0, perrow, tid);

    // ---- load & scale the 12 parameters (overlaps with async loads) ----
    const int gp = active ? g : 0;
    const float* pp = params + (size_t)gp * 14;
    float raw[12];
#pragma unroll
    for (int i = 0; i < 12; i++) raw[i] = pp[i];

    const float BETA  = 1.0f   + raw[0]  * 5.0f;
    const float FC    = 50.0f  + raw[1]  * 950.0f;
    const float K0    = 0.05f  + raw[2]  * 0.85f;
    const float K1    = 0.01f  + raw[3]  * 0.49f;
    const float K2    = 0.001f + raw[4]  * 0.199f;
    const float LP    = 0.2f   + raw[5]  * 0.8f;
    const float PERCp =          raw[6]  * 10.0f;
    const float UZL   =          raw[7]  * 100.0f;
    const float TT    = -2.5f  + raw[8]  * 5.0f;
    const float CFMAX = 0.5f   + raw[9]  * 9.5f;
    const float CFR   =          raw[10] * 0.1f;
    const float CWH   =          raw[11] * 0.2f;

    const float CFRC     = CFR * CFMAX;
    const float CFMAX_TT = CFMAX * TT;     // melt = fma(CFMAX, T, -CFMAX_TT)
    const float CFRC_TT  = CFRC * TT;      // refr = fma(-CFRC, T,  CFRC_TT)
    const float invFC    = 1.0f / FC;
    const float invLPFC  = 1.0f / (LP * FC);
    const float K1C      = 1.0f - K1;
    const float K2C      = 1.0f - K2;

    // ---- state ----
    float SNOWPACK = 1e-3f, MELTWATER = 1e-3f, SM = 1e-3f, SUZ = 1e-3f, SLZ = 1e-3f;
    // soil wetness for step 0, computed from initial SM (identical math)
    float SW = __saturatef(__powf(SM * invFC, BETA));

    float* o = out + g;                    // advances by CHUNK*NGRID per chunk

#pragma unroll 1
    for (int k = 0; k < NCH; k++) {
        // chunk k arrived (chunk k+1 may stay in flight)
        asm volatile("cp.async.wait_group 1;\n" ::: "memory");
        __syncthreads();   // data visible + everyone done reading buffer (k-1)%3

        const float* sb = (const float*)(smem_raw + (k % NBUF) * BUFB) + tid * 3;

        if (active) {
            if (k < NCH - 1) {
#pragma unroll
                for (int s = 0; s < CHUNK; s++) HBV_STEP(s);
                o += (size_t)CHUNK * NGRID;
            } else {
#pragma unroll
                for (int s = 0; s < TAILNS; s++) HBV_STEP(s);
            }
        }

        // stage chunk k+2 into buffer (k+2)%3 == (k-1)%3 (consumed last iter;
        // this iteration's barrier proved all threads are past it)
        const int t2 = (k + 2) * CHUNK;
        if (t2 < NSTEP) {
            stage_chunk(xb, smem_raw + ((k + 2) % NBUF) * BUFB, t2,
                        min(CHUNK, NSTEP - t2), g0, perrow, tid);
        } else {
            // keep the async group count aligned for wait_group 1
            asm volatile("cp.async.commit_group;\n" ::: "memory");
        }
    }
}

extern "C" void kernel_launch(void* const* d_in, const int* in_sizes, int n_in,
                              void* d_out, int out_size)
{
    const float* x      = (const float*)d_in[0];   // (365, 50000, 3)
    const float* params = (const float*)d_in[1];   // (50000, 14)
    float* out = (float*)d_out;                    // (365, 50000, 1)

    static bool attr_set = false;
    if (!attr_set) {
        cudaFuncSetAttribute(hbv_kernel,
                             cudaFuncAttributeMaxDynamicSharedMemorySize,
                             NBUF * BUFB);
        attr_set = true;
    }

    const int blocks = (NGRID + BLK - 1) / BLK;    // 143
    hbv_kernel<<<blocks, BLK, NBUF * BUFB>>>(x, params, out);
}

// round 15
// speedup vs baseline: 1.0017x; 1.0017x over previous
#include <cuda_runtime.h>
#include <cuda_bf16.h>
#include <cstdint>

#define NSTEP   365
#define NGRID   50000
#define PRECS_F 1e-5f
#define BLK     352                     // 11 warps; 143 blocks -> 1 block/SM, balanced
#define CHUNK   16                      // timesteps staged per smem buffer
#define ROWB    (BLK * 12)              // 4224 B of x per timestep per block
#define BUFB    (ROWB * CHUNK)          // 67584 B per buffer
#define NBUF    3                       // triple buffer: 202752 B smem
#define NCH     ((NSTEP + CHUNK - 1) / CHUNK)   // 23 chunks (22 full + 13-step tail)
#define TAILNS  (NSTEP - (NCH - 1) * CHUNK)     // 13

extern __shared__ char smem_raw[];      // NBUF * BUFB

// Stage `nrows` timestep-rows of this block's x slice into sbuf via cp.async.
// Every thread executes the commit (uniform group counting).
__device__ __forceinline__ void stage_chunk(const char* __restrict__ xbase,
                                            char* sbuf, int t0, int nrows,
                                            int g0, int perrow, int tid)
{
    if (tid < perrow) {
        const char* gsrc = xbase + (size_t)t0 * (size_t)(NGRID * 12)
                                 + (size_t)g0 * 12 + (size_t)tid * 16;
        uint32_t sdst = (uint32_t)__cvta_generic_to_shared(sbuf) + tid * 16;
#pragma unroll
        for (int r = 0; r < CHUNK; r++) {
            if (r < nrows) {
                asm volatile("cp.async.cg.shared.global [%0], [%1], 16;\n"
                             :: "r"(sdst + r * ROWB),
                                "l"(gsrc + (size_t)r * (size_t)(NGRID * 12))
                             : "memory");
            }
        }
    }
    asm volatile("cp.async.commit_group;\n" ::: "memory");
}

// One HBV timestep at compile-time step index s. Q for the step is kept in
// qreg[s]; all stores for a chunk are issued in one burst at chunk end so the
// DRAM sees long pure-read stretches instead of per-step read/write
// interleaving (bus-turnaround efficiency).
#define HBV_STEP(s) do {                                                        \
    const float P = sb[(s) * (BLK * 3) + 0];                                    \
    const float T = sb[(s) * (BLK * 3) + 1];                                    \
    const float E = sb[(s) * (BLK * 3) + 2];                                    \
    const float RAIN = (T >= TT) ? P : 0.0f;                                    \
    SNOWPACK += P - RAIN;                                                       \
    const float melt = fminf(fmaxf(fmaf(CFMAX, T, -CFMAX_TT), 0.0f), SNOWPACK); \
    MELTWATER += melt;                                                          \
    SNOWPACK  -= melt;                                                          \
    const float refr = fminf(fmaxf(fmaf(-CFRC, T, CFRC_TT), 0.0f), MELTWATER);  \
    SNOWPACK  += refr;                                                          \
    MELTWATER -= refr;                                                          \
    const float tosoil = fmaxf(fmaf(-CWH, SNOWPACK, MELTWATER), 0.0f);          \
    MELTWATER -= tosoil;                                                        \
    const float rt       = RAIN + tosoil;                                       \
    const float recharge = rt * SW;               /* SW from previous step */   \
    SM += rt - recharge;                                                        \
    const float excess = fmaxf(SM - FC, 0.0f);                                  \
    SM = fminf(SM, FC);                           /* == SM - excess */          \
    const float evapf = __saturatef(SM * invLPFC);                              \
    const float ETact = fminf(SM, E * evapf);                                   \
    SM = fmaxf(SM - ETact, PRECS_F);                                            \
    SW = __saturatef(__powf(SM * invFC, BETA));   /* for NEXT step */           \
    SUZ += recharge + excess;                                                   \
    const float PERC = fminf(SUZ, PERCp);                                       \
    SUZ -= PERC;                                  /* S2 */                      \
    const float suz3 = fmaf(-K0, fmaxf(SUZ - UZL, 0.0f), SUZ) * K1C; /* S4 */   \
    SLZ += PERC;                                  /* L1 */                      \
    const float slz2 = SLZ * K2C;                 /* L2 */                      \
    qreg[s] = (SUZ - suz3) + (SLZ - slz2);        /* Q0+Q1+Q2 telescoped */     \
    SUZ = suz3;                                                                 \
    SLZ = slz2;                                                                 \
} while (0)

__global__ __launch_bounds__(BLK, 1)
void hbv_kernel(const float* __restrict__ x,
                const float* __restrict__ params,
                float* __restrict__ out)
{
    const int tid = threadIdx.x;
    const int g0  = blockIdx.x * BLK;
    const int g   = g0 + tid;
    const bool active = (g < NGRID);

    const int ncells = min(BLK, NGRID - g0);       // 352, or 16 for last block
    const int perrow = (ncells * 12) / 16;         // 16B cp.async ops per row

    // ---- kick off the first two chunk loads immediately (depth-2 prefetch) ----
    const char* xb = (const char*)x;
    stage_chunk(xb, smem_raw,        0,     CHUNK, g0, perrow, tid);
    stage_chunk(xb, smem_raw + BUFB, CHUNK, CHUNK, g0, perrow, tid);

    // ---- load & scale the 12 parameters (overlaps with async loads) ----
    const int gp = active ? g : 0;
    const float* pp = params + (size_t)gp * 14;
    float raw[12];
#pragma unroll
    for (int i = 0; i < 12; i++) raw[i] = pp[i];

    const float BETA  = 1.0f   + raw[0]  * 5.0f;
    const float FC    = 50.0f  + raw[1]  * 950.0f;
    const float K0    = 0.05f  + raw[2]  * 0.85f;
    const float K1    = 0.01f  + raw[3]  * 0.49f;
    const float K2    = 0.001f + raw[4]  * 0.199f;
    const float LP    = 0.2f   + raw[5]  * 0.8f;
    const float PERCp =          raw[6]  * 10.0f;
    const float UZL   =          raw[7]  * 100.0f;
    const float TT    = -2.5f  + raw[8]  * 5.0f;
    const float CFMAX = 0.5f   + raw[9]  * 9.5f;
    const float CFR   =          raw[10] * 0.1f;
    const float CWH   =          raw[11] * 0.2f;

    const float CFRC     = CFR * CFMAX;
    const float CFMAX_TT = CFMAX * TT;     // melt = fma(CFMAX, T, -CFMAX_TT)
    const float CFRC_TT  = CFRC * TT;      // refr = fma(-CFRC, T,  CFRC_TT)
    const float invFC    = 1.0f / FC;
    const float invLPFC  = 1.0f / (LP * FC);
    const float K1C      = 1.0f - K1;
    const float K2C      = 1.0f - K2;

    // ---- state ----
    float SNOWPACK = 1e-3f, MELTWATER = 1e-3f, SM = 1e-3f, SUZ = 1e-3f, SLZ = 1e-3f;
    float SW = __saturatef(__powf(SM * invFC, BETA));   // soil wetness for step 0

    float qreg[CHUNK];                     // per-chunk output accumulator

    float* o = out + g;                    // advances by CHUNK*NGRID per chunk

#pragma unroll 1
    for (int k = 0; k < NCH; k++) {
        // chunk k arrived (chunk k+1 may stay in flight)
        asm volatile("cp.async.wait_group 1;\n" ::: "memory");
        __syncthreads();   // data visible + everyone done reading buffer (k-1)%3

        const float* sb = (const float*)(smem_raw + (k % NBUF) * BUFB) + tid * 3;

        if (active) {
            if (k < NCH - 1) {
#pragma unroll
                for (int s = 0; s < CHUNK; s++) HBV_STEP(s);
                // write burst: 16 stores back-to-back (fire-and-forget)
#pragma unroll
                for (int s = 0; s < CHUNK; s++)
                    __stcs(o + (size_t)s * NGRID, qreg[s]);
                o += (size_t)CHUNK * NGRID;
            } else {
#pragma unroll
                for (int s = 0; s < TAILNS; s++) HBV_STEP(s);
#pragma unroll
                for (int s = 0; s < TAILNS; s++)
                    __stcs(o + (size_t)s * NGRID, qreg[s]);
            }
        }

        // stage chunk k+2 into buffer (k+2)%3 == (k-1)%3 (consumed last iter;
        // this iteration's barrier proved all threads are past it)
        const int t2 = (k + 2) * CHUNK;
        if (t2 < NSTEP) {
            stage_chunk(xb, smem_raw + ((k + 2) % NBUF) * BUFB, t2,
                        min(CHUNK, NSTEP - t2), g0, perrow, tid);
        } else {
            // keep the async group count aligned for wait_group 1
            asm volatile("cp.async.commit_group;\n" ::: "memory");
        }
    }
}

extern "C" void kernel_launch(void* const* d_in, const int* in_sizes, int n_in,
                              void* d_out, int out_size)
{
    const float* x      = (const float*)d_in[0];   // (365, 50000, 3)
    const float* params = (const float*)d_in[1];   // (50000, 14)
    float* out = (float*)d_out;                    // (365, 50000, 1)

    static bool attr_set = false;
    if (!attr_set) {
        cudaFuncSetAttribute(hbv_kernel,
                             cudaFuncAttributeMaxDynamicSharedMemorySize,
                             NBUF * BUFB);
        attr_set = true;
    }

    const int blocks = (NGRID + BLK - 1) / BLK;    // 143
    hbv_kernel<<<blocks, BLK, NBUF * BUFB>>>(x, params, out);
}